// round 12
// baseline (speedup 1.0000x reference)
#include <cuda_runtime.h>
#include <cuda_bf16.h>
#include <mma.h>

using namespace nvcuda;

// ---------------------------------------------------------------------------
// NeuralODEFlow: z' = mlp(z), Euler, log_det via finite-difference trace.
//   trace_step = dt/H * (Sy_new - Sy_old)  +  dt * m1^T Q m2
// with Q[k,i] = W2[k,i]*(W3@W1)[i,k], m1/m2 = ReLU masks at z_new.
//
// R11: k2 fully on tensor cores. u2 = h1@W2 via bf16x3 split-precision
// (6 HMMA products, fp32 accum ~ fp32-class); V = mask@Qb via 1 bf16 HMMA.
// h1 stored as 3 bf16 split planes + mask plane (written by k1); W2 splits
// precomputed. Double-buffered smem mainloop. k3 folded into k1.
// ---------------------------------------------------------------------------

#define BATCH 1024
#define DIM   64
#define HID   512
#define NSTEP 9
#define HSTEP 1e-5f

// scratch (device globals: allocation-free)
__device__ __nv_bfloat16 g_Qb  [HID * HID];
__device__ __nv_bfloat16 g_W2hi[HID * HID];
__device__ __nv_bfloat16 g_W2md[HID * HID];
__device__ __nv_bfloat16 g_W2lo[HID * HID];
__device__ __nv_bfloat16 g_h1hi[BATCH * HID];
__device__ __nv_bfloat16 g_h1md[BATCH * HID];
__device__ __nv_bfloat16 g_h1lo[BATCH * HID];
__device__ __nv_bfloat16 g_h1mk[BATCH * HID];
__device__ float g_z[BATCH * DIM];
__device__ float g_ypart[BATCH * 8 * DIM];   // [row][cb][j]
__device__ float g_part [BATCH * 8];         // bilinear partials
__device__ float g_ysump[BATCH * 8];         // rowsum-of-y partials (excl. b3)
__device__ float g_ysum[2][BATCH];           // Sy per eval (ping-pong)

__device__ __forceinline__ void split3(float v, __nv_bfloat16& b0,
                                       __nv_bfloat16& b1, __nv_bfloat16& b2) {
    b0 = __float2bfloat16(v);
    float r = v - __bfloat162float(b0);
    b1 = __float2bfloat16(r);
    float r2 = r - __bfloat162float(b1);
    b2 = __float2bfloat16(r2);
}

// ---------------------------------------------------------------------------
// k_init: Qb[k,i] = bf16( W2[k,i] * (W3@W1)[i,k] ); zero logdet. grid(8,8).
// ---------------------------------------------------------------------------
__global__ __launch_bounds__(256) void k_init(const float* __restrict__ W1,
                                              const float* __restrict__ W2,
                                              const float* __restrict__ W3,
                                              float* __restrict__ out_logdet) {
    __shared__ float w3t[64][68];
    __shared__ float w1s[64][64];
    int i0 = blockIdx.x * 64, k0 = blockIdx.y * 64;
    int t = threadIdx.x;

#pragma unroll
    for (int q = 0; q < 16; ++q) {
        int e = t + 256 * q;
        int hi = e >> 6, lo = e & 63;
        w3t[lo][hi] = W3[(i0 + hi) * DIM + lo];
        w1s[hi][lo] = W1[hi * HID + k0 + lo];
    }
    __syncthreads();

    int tx = t & 15, ty = t >> 4;
    float acc[4][4];
#pragma unroll
    for (int r = 0; r < 4; ++r)
#pragma unroll
        for (int c = 0; c < 4; ++c) acc[r][c] = 0.f;

#pragma unroll 4
    for (int j = 0; j < 64; ++j) {
        float a[4], b[4];
        *(float4*)a = *(const float4*)&w3t[j][tx * 4];
        *(float4*)b = *(const float4*)&w1s[j][ty * 4];
#pragma unroll
        for (int r = 0; r < 4; ++r)
#pragma unroll
            for (int c = 0; c < 4; ++c) acc[r][c] += b[r] * a[c];
    }

#pragma unroll
    for (int r = 0; r < 4; ++r) {
        int idx = (k0 + ty * 4 + r) * HID + i0 + tx * 4;
        float4 w2v = *(const float4*)&W2[idx];
        __nv_bfloat162 q01 = __floats2bfloat162_rn(w2v.x * acc[r][0], w2v.y * acc[r][1]);
        __nv_bfloat162 q23 = __floats2bfloat162_rn(w2v.z * acc[r][2], w2v.w * acc[r][3]);
        *(__nv_bfloat162*)&g_Qb[idx]     = q01;
        *(__nv_bfloat162*)&g_Qb[idx + 2] = q23;
    }

    if (blockIdx.x == 0 && blockIdx.y == 0) {
        for (int i = t; i < BATCH; i += 256) out_logdet[i] = 0.f;
    }
}

// ---------------------------------------------------------------------------
// k_initW: bf16x3 split of W2. grid 512 (one k-row), 256 threads.
// ---------------------------------------------------------------------------
__global__ __launch_bounds__(256) void k_initW(const float* __restrict__ W2) {
    int k = blockIdx.x;
    for (int c = threadIdx.x; c < HID; c += 256) {
        int idx = k * HID + c;
        __nv_bfloat16 b0, b1, b2;
        split3(W2[idx], b0, b1, b2);
        g_W2hi[idx] = b0;
        g_W2md[idx] = b1;
        g_W2lo[idx] = b2;
    }
}

// ---------------------------------------------------------------------------
// K1: [fused logdet update for previous step] + z Euler update + layer1 GEMM,
// writing h1 as bf16x3 split planes + mask plane.
// grid: 128 blocks * 256 threads, 8 rows per block.
// ---------------------------------------------------------------------------
__global__ __launch_bounds__(256) void k1_layer1(const float* __restrict__ xin,
                                                 const float* __restrict__ W1,
                                                 const float* __restrict__ b1,
                                                 const float* __restrict__ b3,
                                                 float* __restrict__ out_logdet,
                                                 float dt, float dtPrev,
                                                 int syNew, int syOld,
                                                 int first, int dolog) {
    __shared__ float zs[8 * 64];
    int row0 = blockIdx.x * 8;
    int t = threadIdx.x;

    // fused per-row bookkeeping: Sy_{e-1} = sum_cb ysump; logdet update (step e-1)
    if (!first && t < 8) {
        int row = row0 + t;
        float sy = 0.f, bl = 0.f;
#pragma unroll
        for (int cbk = 0; cbk < 8; ++cbk) {
            sy += g_ysump[row * 8 + cbk];
            bl += g_part [row * 8 + cbk];
        }
        if (dolog) {
            float tr = (sy - g_ysum[syOld][row]) * (dtPrev / HSTEP) + bl * dtPrev;
            out_logdet[row] -= tr;
        }
        g_ysum[syNew][row] = sy;
    }

#pragma unroll
    for (int q = 0; q < 2; ++q) {
        int idx = t + 256 * q;               // 0..511
        int g = row0 * DIM + idx;
        float z;
        if (first) {
            z = xin[g];
        } else {
            int row = row0 + (idx >> 6), j = idx & 63;
            float s = 0.f;
#pragma unroll
            for (int cbk = 0; cbk < 8; ++cbk)
                s += g_ypart[(row * 8 + cbk) * DIM + j];
            z = g_z[g] + dt * (s + b3[j]);
        }
        zs[idx] = z;
        g_z[g] = z;
    }
    __syncthreads();

    float acc0[8], acc1[8];
#pragma unroll
    for (int r = 0; r < 8; ++r) { acc0[r] = 0.f; acc1[r] = 0.f; }
    int c0 = t, c1 = t + 256;
#pragma unroll 4
    for (int k = 0; k < 64; ++k) {
        float wa = W1[k * HID + c0];
        float wb = W1[k * HID + c1];
#pragma unroll
        for (int r = 0; r < 8; ++r) {
            float z = zs[r * 64 + k];
            acc0[r] += z * wa;
            acc1[r] += z * wb;
        }
    }
    float ba = b1[c0], bb = b1[c1];
    const __nv_bfloat16 bONE = __float2bfloat16(1.f);
    const __nv_bfloat16 bZERO = __float2bfloat16(0.f);
#pragma unroll
    for (int r = 0; r < 8; ++r) {
        int i0 = (row0 + r) * HID + c0;
        int i1 = (row0 + r) * HID + c1;
        float u0 = acc0[r] + ba, u1 = acc1[r] + bb;
        float v0 = fmaxf(u0, 0.f), v1 = fmaxf(u1, 0.f);
        __nv_bfloat16 s0, s1, s2;
        split3(v0, s0, s1, s2);
        g_h1hi[i0] = s0; g_h1md[i0] = s1; g_h1lo[i0] = s2;
        g_h1mk[i0] = (u0 > 0.f) ? bONE : bZERO;
        split3(v1, s0, s1, s2);
        g_h1hi[i1] = s0; g_h1md[i1] = s1; g_h1lo[i1] = s2;
        g_h1mk[i1] = (u1 > 0.f) ? bONE : bZERO;
    }
}

// ---------------------------------------------------------------------------
// K2: tensor-core dual GEMM over 64x64 tiles, K=512, BK=16, grid (8,16):
//   u2 = h1 @ W2   (bf16x3: 6 HMMA products, fp32 accum)
//   V  = mask @ Qb (1 bf16 HMMA)
// Epilogue (fp32): h2 = relu(u2+b2); bilinear partial; ypart = h2 @ W3tile;
// rowsum partials. Double-buffered smem; register prefetch.
// ---------------------------------------------------------------------------
__global__ __launch_bounds__(256) void k2_layer2(const float* __restrict__ b2,
                                                 const float* __restrict__ W3) {
    __shared__ float sm[9728];                       // 38.9 KB, unioned
    // mainloop stages: 8192 bf16 each (A planes 0..4095, B planes 4096..8191)
    __nv_bfloat16* st0 = (__nv_bfloat16*)sm;
    __nv_bfloat16* st1 = (__nv_bfloat16*)(sm + 4096);

    int cb = blockIdx.x, rb = blockIdx.y;
    int row0 = rb * 64, col0 = cb * 64;
    int t = threadIdx.x;
    int warp = t >> 5;
    int rowblk = warp & 3, colgrp = warp >> 2;

    wmma::fragment<wmma::matrix_a, 16, 16, 16, __nv_bfloat16, wmma::row_major> fahi, famd, falo, famk;
    wmma::fragment<wmma::matrix_b, 16, 16, 16, __nv_bfloat16, wmma::row_major> fb;
    wmma::fragment<wmma::accumulator, 16, 16, 16, float> fcu[2], fcv[2];
    wmma::fill_fragment(fcu[0], 0.f); wmma::fill_fragment(fcu[1], 0.f);
    wmma::fill_fragment(fcv[0], 0.f); wmma::fill_fragment(fcv[1], 0.f);

    // global load lanes
    int arow = t >> 2, aseg = t & 3;     // A: uint2 (4 bf16) per plane
    int brow = t >> 4, bseg = t & 15;    // B: uint2 per plane
    const __nv_bfloat16* aP[4] = {
        g_h1hi + (row0 + arow) * HID + aseg * 4,
        g_h1md + (row0 + arow) * HID + aseg * 4,
        g_h1lo + (row0 + arow) * HID + aseg * 4,
        g_h1mk + (row0 + arow) * HID + aseg * 4 };
    const __nv_bfloat16* bP[4] = {
        g_W2hi + brow * HID + col0 + bseg * 4,
        g_W2md + brow * HID + col0 + bseg * 4,
        g_W2lo + brow * HID + col0 + bseg * 4,
        g_Qb   + brow * HID + col0 + bseg * 4 };
    int sA = arow * 16 + aseg * 4;
    int sB = brow * 64 + bseg * 4;

    // tile 0 -> stage 0
#pragma unroll
    for (int p = 0; p < 4; ++p) {
        *(uint2*)&st0[p * 1024 + sA]        = *(const uint2*)aP[p];
        *(uint2*)&st0[4096 + p * 1024 + sB] = *(const uint2*)bP[p];
    }
    __syncthreads();

    int buf = 0;
#pragma unroll 1
    for (int k0 = 0; k0 < HID; k0 += 16) {
        uint2 pA[4], pB[4];
        bool more = (k0 + 16 < HID);
        if (more) {
#pragma unroll
            for (int p = 0; p < 4; ++p) {
                pA[p] = *(const uint2*)(aP[p] + (k0 + 16));
                pB[p] = *(const uint2*)(bP[p] + (k0 + 16) * HID);
            }
        }
        __nv_bfloat16* S = buf ? st1 : st0;

        wmma::load_matrix_sync(fahi, S + 0    + rowblk * 256, 16);
        wmma::load_matrix_sync(famd, S + 1024 + rowblk * 256, 16);
        wmma::load_matrix_sync(falo, S + 2048 + rowblk * 256, 16);
        wmma::load_matrix_sync(famk, S + 3072 + rowblk * 256, 16);
#pragma unroll
        for (int ct = 0; ct < 2; ++ct) {
            int c = colgrp * 32 + ct * 16;
            wmma::load_matrix_sync(fb, S + 4096 + c, 64);           // W2 hi
            wmma::mma_sync(fcu[ct], fahi, fb, fcu[ct]);
            wmma::mma_sync(fcu[ct], famd, fb, fcu[ct]);
            wmma::mma_sync(fcu[ct], falo, fb, fcu[ct]);
            wmma::load_matrix_sync(fb, S + 5120 + c, 64);           // W2 mid
            wmma::mma_sync(fcu[ct], fahi, fb, fcu[ct]);
            wmma::mma_sync(fcu[ct], famd, fb, fcu[ct]);
            wmma::load_matrix_sync(fb, S + 6144 + c, 64);           // W2 lo
            wmma::mma_sync(fcu[ct], fahi, fb, fcu[ct]);
            wmma::load_matrix_sync(fb, S + 7168 + c, 64);           // Qb
            wmma::mma_sync(fcv[ct], famk, fb, fcv[ct]);
        }

        if (more) {
            __nv_bfloat16* D = buf ? st0 : st1;
#pragma unroll
            for (int p = 0; p < 4; ++p) {
                *(uint2*)&D[p * 1024 + sA]        = pA[p];
                *(uint2*)&D[4096 + p * 1024 + sB] = pB[p];
            }
        }
        __syncthreads();
        buf ^= 1;
    }

    int tx = t & 15, ty = t >> 4;

    // V roundtrip -> av regs
    wmma::store_matrix_sync(sm + (rowblk * 16) * 68 + colgrp * 32,      fcv[0], 68, wmma::mem_row_major);
    wmma::store_matrix_sync(sm + (rowblk * 16) * 68 + colgrp * 32 + 16, fcv[1], 68, wmma::mem_row_major);
    __syncthreads();
    float av[4][4];
#pragma unroll
    for (int r = 0; r < 4; ++r)
#pragma unroll
        for (int c = 0; c < 4; ++c) av[r][c] = sm[(ty * 4 + r) * 68 + tx * 4 + c];
    __syncthreads();

    // U roundtrip -> au regs
    wmma::store_matrix_sync(sm + (rowblk * 16) * 68 + colgrp * 32,      fcu[0], 68, wmma::mem_row_major);
    wmma::store_matrix_sync(sm + (rowblk * 16) * 68 + colgrp * 32 + 16, fcu[1], 68, wmma::mem_row_major);
    __syncthreads();
    float au[4][4];
#pragma unroll
    for (int r = 0; r < 4; ++r)
#pragma unroll
        for (int c = 0; c < 4; ++c) au[r][c] = sm[(ty * 4 + r) * 68 + tx * 4 + c];
    __syncthreads();

    // ---- epilogue phase 1: h2 tile -> smem, bilinear partial -> RED, W3 tile
#define H2S(r_, c_)  sm[(r_) * 68 + (c_)]
#define W3S(k_, j_)  sm[4352 + (k_) * 68 + (j_)]
#define RED(x_, y_)  sm[8704 + (x_) * 64 + (y_)]
    float b2v[4];
    *(float4*)b2v = *(const float4*)&b2[col0 + tx * 4];
#pragma unroll
    for (int r = 0; r < 4; ++r) {
        float h2v[4];
        float s = 0.f;
#pragma unroll
        for (int c = 0; c < 4; ++c) {
            float u = au[r][c] + b2v[c];
            h2v[c] = fmaxf(u, 0.f);
            s += (u > 0.f) ? av[r][c] : 0.f;
        }
        *(float4*)&H2S(ty * 4 + r, tx * 4) = *(float4*)h2v;
        RED(tx, ty * 4 + r) = s;
    }
#pragma unroll
    for (int q = 0; q < 4; ++q) {
        int f = t + 256 * q;              // float4 index 0..1023
        int k = f >> 4, j4 = (f & 15) * 4;
        *(float4*)&W3S(k, j4) = *(const float4*)&W3[(col0 + k) * DIM + j4];
    }
    __syncthreads();

    // ---- epilogue phase 2: ypart = h2_tile @ W3_tile (fp32)
    float ay[4][4];
#pragma unroll
    for (int r = 0; r < 4; ++r)
#pragma unroll
        for (int c = 0; c < 4; ++c) ay[r][c] = 0.f;

#pragma unroll 8
    for (int k = 0; k < 64; ++k) {
        float a[4], w[4];
#pragma unroll
        for (int r = 0; r < 4; ++r) a[r] = H2S(ty * 4 + r, k);
        *(float4*)w = *(const float4*)&W3S(k, tx * 4);
#pragma unroll
        for (int r = 0; r < 4; ++r)
#pragma unroll
            for (int c = 0; c < 4; ++c) ay[r][c] += a[r] * w[c];
    }
#pragma unroll
    for (int r = 0; r < 4; ++r) {
        int row = row0 + ty * 4 + r;
        *(float4*)&g_ypart[(row * 8 + cb) * DIM + tx * 4] = *(float4*)ay[r];
    }

    // bilinear partial reduction
    if (t < 64) {
        float s = 0.f;
#pragma unroll
        for (int x = 0; x < 16; ++x) s += RED(x, t);
        g_part[(row0 + t) * 8 + cb] = s;
    }
    __syncthreads();

    // rowsum-of-y partials
#pragma unroll
    for (int r = 0; r < 4; ++r)
        RED(tx, ty * 4 + r) = ay[r][0] + ay[r][1] + ay[r][2] + ay[r][3];
    __syncthreads();
    if (t < 64) {
        float s = 0.f;
#pragma unroll
        for (int x = 0; x < 16; ++x) s += RED(x, t);
        g_ysump[(row0 + t) * 8 + cb] = s;
    }
#undef H2S
#undef W3S
#undef RED
}

// ---------------------------------------------------------------------------
// K3t: final-step logdet update (step NSTEP). grid 4 * 256.
// ---------------------------------------------------------------------------
__global__ __launch_bounds__(256) void k3_tiny(float* __restrict__ out_logdet,
                                               float dt, int newIdx) {
    int row = blockIdx.x * 256 + threadIdx.x;
    float sy = 0.f, bl = 0.f;
#pragma unroll
    for (int cbk = 0; cbk < 8; ++cbk) {
        sy += g_ysump[row * 8 + cbk];
        bl += g_part [row * 8 + cbk];
    }
    float trace = (sy - g_ysum[newIdx ^ 1][row]) * (dt / HSTEP) + bl * dt;
    out_logdet[row] -= trace;
}

// final z copy into d_out
__global__ __launch_bounds__(256) void k_final(float* __restrict__ out) {
    int i = blockIdx.x * 256 + threadIdx.x;
    out[i] = g_z[i];
}

// ---------------------------------------------------------------------------
extern "C" void kernel_launch(void* const* d_in, const int* in_sizes, int n_in,
                              void* d_out, int out_size) {
    (void)in_sizes; (void)n_in; (void)out_size;
    const float* x  = (const float*)d_in[0];
    const float* W1 = (const float*)d_in[1];
    const float* b1 = (const float*)d_in[2];
    const float* W2 = (const float*)d_in[3];
    const float* b2 = (const float*)d_in[4];
    const float* W3 = (const float*)d_in[5];
    const float* b3 = (const float*)d_in[6];
    float* out        = (float*)d_out;
    float* out_logdet = out + BATCH * DIM;

    float tt[NSTEP + 1];
    for (int i = 0; i <= NSTEP; ++i) tt[i] = (float)i / 9.0f;

    dim3 g2(8, 16);
    dim3 gi(8, 8);

    k_init<<<gi, 256>>>(W1, W2, W3, out_logdet);
    k_initW<<<512, 256>>>(W2);

    // eval 0 at z = x
    k1_layer1<<<128, 256>>>(x, W1, b1, b3, out_logdet, 0.f, 0.f, 0, 0, 1, 0);
    k2_layer2<<<g2, 256>>>(b2, W3);

    // evals 1..9 (Euler steps); k1(e_s) also finalizes step s-1's logdet
    for (int s = 1; s <= NSTEP; ++s) {
        float dt = tt[s] - tt[s - 1];
        float dtPrev = (s >= 2) ? (tt[s - 1] - tt[s - 2]) : 0.f;
        int syNew = (s - 1) & 1;
        int syOld = (s >= 2) ? ((s - 2) & 1) : 0;
        int dolog = (s >= 2) ? 1 : 0;
        k1_layer1<<<128, 256>>>(x, W1, b1, b3, out_logdet, dt, dtPrev,
                                syNew, syOld, 0, dolog);
        k2_layer2<<<g2, 256>>>(b2, W3);
    }

    // final step-9 logdet update (Sy_9 vs Sy_8 at slot 0)
    k3_tiny<<<4, 256>>>(out_logdet, tt[NSTEP] - tt[NSTEP - 1], 1);

    k_final<<<256, 256>>>(out);
}